// round 15
// baseline (speedup 1.0000x reference)
#include <cuda_runtime.h>
#include <cuda_bf16.h>
#include <math.h>

#define B_   8
#define S_   2048
#define DIN  1024
#define DK   64
#define MTOT (B_ * S_)
#define NFUS 192
#define NSP  4                     // split-KV factor

// bf16 hi/lo planes (u32 = 2 packed bf16 along contraction dim)
__device__ unsigned g_Whi[NFUS * DIN / 2], g_Wlo[NFUS * DIN / 2];   // [n][k/2]
__device__ unsigned g_Qhi[MTOT * 32], g_Qlo[MTOT * 32];             // x 0.125*log2(e)
__device__ unsigned g_Khi[MTOT * 32], g_Klo[MTOT * 32];
__device__ unsigned g_Vthi[B_ * 64 * 1024], g_Vtlo[B_ * 64 * 1024]; // [b][dim][kv/2]
// split-KV partials (max-free softmax)
__device__ float g_Op[NSP * MTOT * DK];
__device__ float g_pl[NSP * MTOT];

__device__ __forceinline__ unsigned pack_bf16(__nv_bfloat16 lo, __nv_bfloat16 hi)
{
    return (unsigned)__bfloat16_as_ushort(lo) |
           ((unsigned)__bfloat16_as_ushort(hi) << 16);
}
// hi/lo bf16 split of a float pair (RN, identical to __float2bfloat16).
__device__ __forceinline__ void split2(float a, float b, unsigned& hi, unsigned& lo)
{
    unsigned h;
    asm("cvt.rn.bf16x2.f32 %0, %1, %2;" : "=r"(h) : "f"(b), "f"(a));
    const float fa = __uint_as_float(h << 16);
    const float fb = __uint_as_float(h & 0xffff0000u);
    unsigned l;
    asm("cvt.rn.bf16x2.f32 %0, %1, %2;" : "=r"(l) : "f"(b - fb), "f"(a - fa));
    hi = h;
    lo = l;
}
__device__ __forceinline__ float ex2f(float x)
{
    float r;
    asm("ex2.approx.f32 %0, %1;" : "=f"(r) : "f"(x));
    return r;
}
__device__ __forceinline__ void mma_bf16(float c[4], const unsigned a[4],
                                         unsigned b0, unsigned b1)
{
    asm volatile(
        "mma.sync.aligned.m16n8k16.row.col.f32.bf16.bf16.f32 "
        "{%0,%1,%2,%3},{%4,%5,%6,%7},{%8,%9},{%0,%1,%2,%3};"
        : "+f"(c[0]), "+f"(c[1]), "+f"(c[2]), "+f"(c[3])
        : "r"(a[0]), "r"(a[1]), "r"(a[2]), "r"(a[3]), "r"(b0), "r"(b1));
}
__device__ __forceinline__ void ldm_x4(unsigned r[4], const unsigned* p)
{
    unsigned sa = (unsigned)__cvta_generic_to_shared(p);
    asm volatile("ldmatrix.sync.aligned.m8n8.x4.shared.b16 {%0,%1,%2,%3}, [%4];"
                 : "=r"(r[0]), "=r"(r[1]), "=r"(r[2]), "=r"(r[3]) : "r"(sa));
}
__device__ __forceinline__ void cp16(unsigned* smem_dst, const unsigned* gmem_src)
{
    unsigned sa = (unsigned)__cvta_generic_to_shared(smem_dst);
    asm volatile("cp.async.cg.shared.global [%0], [%1], 16;" :: "r"(sa), "l"(gmem_src));
}
#define CP_COMMIT() asm volatile("cp.async.commit_group;")
#define CP_WAIT0()  asm volatile("cp.async.wait_group 0;")
#define CP_WAIT1()  asm volatile("cp.async.wait_group 1;")

// ---------------------------------------------------------------------------
// W -> transposed bf16 hi/lo planes [192][1024]. Coalesced via smem transpose.
// ---------------------------------------------------------------------------
__global__ __launch_bounds__(256) void cvt_w_kernel(
    const float* __restrict__ Wq, const float* __restrict__ Wk,
    const float* __restrict__ Wv)
{
    __shared__ float sm[64 * 130];
    const int kblk = blockIdx.x;
    const int mat  = blockIdx.y;
    const float* Wsrc = (mat == 0) ? Wq : (mat == 1) ? Wk : Wv;
    const int t = threadIdx.x;

#pragma unroll
    for (int j = 0; j < 8; j++) {
        const int lin = j * 256 + t;
        const int r = lin >> 4, q = lin & 15;
        float4 v = *(const float4*)&Wsrc[(size_t)(kblk * 128 + r) * 64 + q * 4];
        sm[(q * 4 + 0) * 130 + r] = v.x;
        sm[(q * 4 + 1) * 130 + r] = v.y;
        sm[(q * 4 + 2) * 130 + r] = v.z;
        sm[(q * 4 + 3) * 130 + r] = v.w;
    }
    __syncthreads();

#pragma unroll
    for (int j = 0; j < 16; j++) {
        const int lin = j * 256 + t;
        const int n = lin >> 6, ku = lin & 63;
        unsigned hi, lo;
        split2(sm[n * 130 + 2 * ku], sm[n * 130 + 2 * ku + 1], hi, lo);
        const size_t o = (size_t)(mat * 64 + n) * 512 + kblk * 64 + ku;
        g_Whi[o] = hi;
        g_Wlo[o] = lo;
    }
}

// ---------------------------------------------------------------------------
// Pipelined bf16x3 QKV GEMM, fused X conversion, fused Vt transpose epilogue.
// CTA 128 rows x 96 cols, 256 thr (8 warps: wm 4 x wn 2, warp 32x48).
// ---------------------------------------------------------------------------
#define QP     20
#define QS_XH  0
#define QS_XL  (128 * QP)
#define QS_WH  (256 * QP)
#define QS_WL  (352 * QP)
#define QSTAGE (448 * QP)      // 8960 u32 = 35840 B

__global__ __launch_bounds__(256, 2) void qkv_mma_kernel(const float* __restrict__ X)
{
    extern __shared__ unsigned smq[];
    const int t    = threadIdx.x;
    const int lane = t & 31;
    const int w    = t >> 5;
    const int wm   = w & 3;
    const int wn   = w >> 2;
    const int g    = lane >> 2;
    const int tig  = lane & 3;
    const int m0   = (blockIdx.x >> 1) * 128;
    const int n0   = (blockIdx.x & 1) * 96;
    const int lrow = lane & 7;
    const int lt   = lane >> 3;

    float C[2][6][4];
#pragma unroll
    for (int a = 0; a < 2; a++)
#pragma unroll
        for (int b = 0; b < 6; b++)
#pragma unroll
            for (int c = 0; c < 4; c++) C[a][b][c] = 0.0f;

    float4 xreg[4];
    auto loadX = [&](int kc) {
#pragma unroll
        for (int j = 0; j < 4; j++) {
            const int lin = j * 256 + t;
            const int r = lin >> 3, q = lin & 7;
            xreg[j] = *(const float4*)&X[(size_t)(m0 + r) * DIN + kc * 32 + q * 4];
        }
    };
    auto stX = [&](int stg) {
        unsigned* dst = smq + stg * QSTAGE;
#pragma unroll
        for (int j = 0; j < 4; j++) {
            const int lin = j * 256 + t;
            const int r = lin >> 3, q = lin & 7;
            unsigned h0, l0, h1, l1;
            split2(xreg[j].x, xreg[j].y, h0, l0);
            split2(xreg[j].z, xreg[j].w, h1, l1);
            *(uint2*)&dst[QS_XH + r * QP + q * 2] = make_uint2(h0, h1);
            *(uint2*)&dst[QS_XL + r * QP + q * 2] = make_uint2(l0, l1);
        }
    };
    auto cpW = [&](int stg, int kc) {
        unsigned* dst = smq + stg * QSTAGE;
#pragma unroll
        for (int j = 0; j < 3; j++) {
            const int lin = j * 256 + t;
            const int plane = lin / 384, rem = lin - plane * 384;
            const int r = rem >> 2, sg = rem & 3;
            const unsigned* src = plane ? g_Wlo : g_Whi;
            cp16(dst + (plane ? QS_WL : QS_WH) + r * QP + sg * 4,
                 src + (size_t)(n0 + r) * 512 + kc * 16 + sg * 4);
        }
    };

    loadX(0);
    cpW(0, 0);
    CP_COMMIT();
    stX(0);
    CP_WAIT0();
    __syncthreads();

    for (int kc = 0; kc < 32; kc++) {
        const int stg = kc & 1;
        const unsigned* ST = smq + stg * QSTAGE;
        const bool more = (kc + 1 < 32);
        if (more) {
            loadX(kc + 1);
            cpW(stg ^ 1, kc + 1);
            CP_COMMIT();
        }

        unsigned aH[2][2][4], aL[2][2][4];
#pragma unroll
        for (int ks = 0; ks < 2; ks++)
#pragma unroll
            for (int mt = 0; mt < 2; mt++) {
                const int off = (wm * 32 + mt * 16 + (lt & 1) * 8 + lrow) * QP
                              + 8 * ks + 4 * (lt >> 1);
                ldm_x4(aH[ks][mt], ST + QS_XH + off);
                ldm_x4(aL[ks][mt], ST + QS_XL + off);
            }

        unsigned bh[2][4], bl[2][4];
        {
            const int b0 = (wn * 48 + lrow) * QP + 4 * lt;
            ldm_x4(bh[0], ST + QS_WH + b0);
            ldm_x4(bl[0], ST + QS_WL + b0);
        }
#pragma unroll
        for (int nt = 0; nt < 6; nt++) {
            const int cur = nt & 1;
            if (nt < 5) {
                const int bn = (wn * 48 + (nt + 1) * 8 + lrow) * QP + 4 * lt;
                ldm_x4(bh[cur ^ 1], ST + QS_WH + bn);
                ldm_x4(bl[cur ^ 1], ST + QS_WL + bn);
            }
#pragma unroll
            for (int ks = 0; ks < 2; ks++) {
                mma_bf16(C[0][nt], aH[ks][0], bh[cur][2 * ks], bh[cur][2 * ks + 1]);
                mma_bf16(C[1][nt], aH[ks][1], bh[cur][2 * ks], bh[cur][2 * ks + 1]);
                mma_bf16(C[0][nt], aH[ks][0], bl[cur][2 * ks], bl[cur][2 * ks + 1]);
                mma_bf16(C[1][nt], aH[ks][1], bl[cur][2 * ks], bl[cur][2 * ks + 1]);
                mma_bf16(C[0][nt], aL[ks][0], bh[cur][2 * ks], bh[cur][2 * ks + 1]);
                mma_bf16(C[1][nt], aL[ks][1], bh[cur][2 * ks], bh[cur][2 * ks + 1]);
            }
        }

        if (more) {
            stX(stg ^ 1);
            CP_WAIT0();
        }
        __syncthreads();
    }

    // Epilogue: Q x 0.125*log2e; K planes; V transposed to g_Vt (fused).
    __nv_bfloat16* vs_h = (__nv_bfloat16*)smq;          // [64][130]
    __nv_bfloat16* vs_l = vs_h + 64 * 130;

#pragma unroll
    for (int nt = 0; nt < 6; nt++) {
        const int col = n0 + wn * 48 + nt * 8 + tig * 2;
        const int mat = col >> 6;
        if (mat < 2) {
            const int idx = (col & 63) >> 1;
            unsigned* dhi = (mat == 0) ? g_Qhi : g_Khi;
            unsigned* dlo = (mat == 0) ? g_Qlo : g_Klo;
            const float sc = (mat == 0) ? 0.18033688f : 1.0f;  // 0.125*log2(e)
#pragma unroll
            for (int mt = 0; mt < 2; mt++) {
                const int row = m0 + wm * 32 + mt * 16 + g;
                unsigned hi, lo;
                split2(C[mt][nt][0] * sc, C[mt][nt][1] * sc, hi, lo);
                dhi[(size_t)row * 32 + idx] = hi;
                dlo[(size_t)row * 32 + idx] = lo;
                split2(C[mt][nt][2] * sc, C[mt][nt][3] * sc, hi, lo);
                dhi[(size_t)(row + 8) * 32 + idx] = hi;
                dlo[(size_t)(row + 8) * 32 + idx] = lo;
            }
        } else {
            const int d = col & 63;
#pragma unroll
            for (int mt = 0; mt < 2; mt++) {
                const int r = wm * 32 + mt * 16 + g;
                unsigned hi, lo;
                split2(C[mt][nt][0], C[mt][nt][1], hi, lo);
                vs_h[d * 130 + r]       = __ushort_as_bfloat16((unsigned short)(hi & 0xffff));
                vs_h[(d + 1) * 130 + r] = __ushort_as_bfloat16((unsigned short)(hi >> 16));
                vs_l[d * 130 + r]       = __ushort_as_bfloat16((unsigned short)(lo & 0xffff));
                vs_l[(d + 1) * 130 + r] = __ushort_as_bfloat16((unsigned short)(lo >> 16));
                split2(C[mt][nt][2], C[mt][nt][3], hi, lo);
                vs_h[d * 130 + r + 8]       = __ushort_as_bfloat16((unsigned short)(hi & 0xffff));
                vs_h[(d + 1) * 130 + r + 8] = __ushort_as_bfloat16((unsigned short)(hi >> 16));
                vs_l[d * 130 + r + 8]       = __ushort_as_bfloat16((unsigned short)(lo & 0xffff));
                vs_l[(d + 1) * 130 + r + 8] = __ushort_as_bfloat16((unsigned short)(lo >> 16));
            }
        }
    }
    __syncthreads();

    if (n0 == 96) {
        const int b   = m0 >> 11;
        const int kvb = (m0 & 2047) >> 1;
#pragma unroll
        for (int i = 0; i < 32; i++) {
            const int lin = i * 256 + t;
            const int plane = lin >> 12;
            const int rem = lin & 4095;
            const int d = rem >> 6, j = rem & 63;
            const __nv_bfloat16* src = plane ? vs_l : vs_h;
            unsigned v = pack_bf16(src[d * 130 + 2 * j], src[d * 130 + 2 * j + 1]);
            (plane ? g_Vtlo : g_Vthi)[(size_t)(b * 64 + d) * 1024 + kvb + j] = v;
        }
    }
}

// ---------------------------------------------------------------------------
// Pipelined HMMA flash attention, causal, 4-way split-KV, max-free exp2
// softmax. CTA = 128 q-rows, 256 thr. Grid 512. 3-stage cp.async pipeline.
// ---------------------------------------------------------------------------
#define AP     36
#define AS_KH  0
#define AS_KL  (64 * AP)
#define AS_VH  (128 * AP)
#define AS_VL  (192 * AP)
#define ASTAGE (256 * AP)     // 9216 u32 = 36 KB

#define LDB4(H, L, HOFF, LOFF, base) do {          \
    ldm_x4(H,     ST + (HOFF) + (base));           \
    ldm_x4((H) + 4, ST + (HOFF) + (base) + 16);    \
    ldm_x4(L,     ST + (LOFF) + (base));           \
    ldm_x4((L) + 4, ST + (LOFF) + (base) + 16);    \
} while (0)

__global__ __launch_bounds__(256, 2) void attn_kernel()
{
    extern __shared__ unsigned sma[];
    const int bx = blockIdx.x;
    const int b  = bx & 7;
    const int sp = (bx >> 3) & 3;
    const int qt = 15 - (bx >> 5);
    const int t  = threadIdx.x;
    const int lane = t & 31;
    const int w    = t >> 5;
    const int g    = lane >> 2;
    const int tig  = lane & 3;
    const int q0 = qt * 128;
    const int lrow = lane & 7;
    const int lt   = lane >> 3;

    const int rowg  = q0 + w * 16 + g;
    const int grow0 = b * S_ + rowg;
    const int last  = 2 * qt + 1;
    const int ntile = (last >= sp) ? ((last - sp) >> 2) + 1 : 0;

    unsigned qh[4][4], ql[4][4];
#pragma unroll
    for (int ks = 0; ks < 4; ks++) {
        const int i0 = 8 * ks + tig;
        qh[ks][0] = g_Qhi[(size_t)grow0 * 32 + i0];
        qh[ks][1] = g_Qhi[(size_t)(grow0 + 8) * 32 + i0];
        qh[ks][2] = g_Qhi[(size_t)grow0 * 32 + i0 + 4];
        qh[ks][3] = g_Qhi[(size_t)(grow0 + 8) * 32 + i0 + 4];
        ql[ks][0] = g_Qlo[(size_t)grow0 * 32 + i0];
        ql[ks][1] = g_Qlo[(size_t)(grow0 + 8) * 32 + i0];
        ql[ks][2] = g_Qlo[(size_t)grow0 * 32 + i0 + 4];
        ql[ks][3] = g_Qlo[(size_t)(grow0 + 8) * 32 + i0 + 4];
    }

    float O[8][4];
#pragma unroll
    for (int nb = 0; nb < 8; nb++)
#pragma unroll
        for (int c = 0; c < 4; c++) O[nb][c] = 0.0f;
    float l0v = 0.0f, l1v = 0.0f;

    auto fillA = [&](int stg, int kt) {
        unsigned* dst = sma + stg * ASTAGE;
#pragma unroll
        for (int j = 0; j < 8; j++) {
            const int lin = j * 256 + t;
            const int pl  = lin >> 9;
            const int rem = lin & 511;
            const int r = rem >> 3, sg = rem & 7;
            const unsigned* src;
            size_t off;
            int doff;
            if (pl < 2) {
                src = pl ? g_Klo : g_Khi;
                off = (size_t)(b * 2048 + kt * 64 + r) * 32 + sg * 4;
                doff = pl ? AS_KL : AS_KH;
            } else {
                src = (pl == 3) ? g_Vtlo : g_Vthi;
                off = (size_t)(b * 64 + r) * 1024 + kt * 32 + sg * 4;
                doff = (pl == 3) ? AS_VL : AS_VH;
            }
            cp16(dst + doff + r * AP + sg * 4, src + off);
        }
    };

    if (ntile > 0) { fillA(0, sp);     CP_COMMIT(); }
    if (ntile > 1) { fillA(1, sp + 4); CP_COMMIT(); }

    int stg = 0;
    for (int it = 0; it < ntile; it++) {
        const int kt = sp + it * 4;
        if (it == ntile - 1) { CP_WAIT0(); } else { CP_WAIT1(); }
        __syncthreads();
        if (it + 2 < ntile) {
            fillA((stg + 2) % 3, kt + 8);
            CP_COMMIT();
        }
        const unsigned* ST = sma + stg * ASTAGE;

        float S[8][4];
#pragma unroll
        for (int nb = 0; nb < 8; nb++)
#pragma unroll
            for (int c = 0; c < 4; c++) S[nb][c] = 0.0f;

        {
            unsigned kh[2][8], kl[2][8];
            LDB4(kh[0], kl[0], AS_KH, AS_KL, (lrow) * AP + 4 * lt);
#pragma unroll
            for (int nb = 0; nb < 8; nb++) {
                const int cur = nb & 1;
                if (nb < 7)
                    LDB4(kh[cur ^ 1], kl[cur ^ 1], AS_KH, AS_KL,
                         ((nb + 1) * 8 + lrow) * AP + 4 * lt);
#pragma unroll
                for (int ks = 0; ks < 4; ks++)
                    mma_bf16(S[nb], qh[ks], kh[cur][2 * ks], kh[cur][2 * ks + 1]);
#pragma unroll
                for (int ks = 0; ks < 4; ks++)
                    mma_bf16(S[nb], qh[ks], kl[cur][2 * ks], kl[cur][2 * ks + 1]);
#pragma unroll
                for (int ks = 0; ks < 4; ks++)
                    mma_bf16(S[nb], ql[ks], kh[cur][2 * ks], kh[cur][2 * ks + 1]);
            }
        }

        if (kt * 64 + 63 > rowg) {
#pragma unroll
            for (int nb = 0; nb < 8; nb++) {
                const int c0 = kt * 64 + nb * 8 + 2 * tig;
                if (c0 > rowg)         S[nb][0] = -INFINITY;
                if (c0 + 1 > rowg)     S[nb][1] = -INFINITY;
                if (c0 > rowg + 8)     S[nb][2] = -INFINITY;
                if (c0 + 1 > rowg + 8) S[nb][3] = -INFINITY;
            }
        }

        unsigned ph[4][4], pl_[4][4];
#pragma unroll
        for (int nb = 0; nb < 8; nb++) {
            const float p00 = ex2f(S[nb][0]);
            const float p01 = ex2f(S[nb][1]);
            const float p10 = ex2f(S[nb][2]);
            const float p11 = ex2f(S[nb][3]);
            l0v += p00 + p01;
            l1v += p10 + p11;
            const int ks = nb >> 1;
            const int hf = (nb & 1) * 2;
            split2(p00, p01, ph[ks][hf + 0], pl_[ks][hf + 0]);
            split2(p10, p11, ph[ks][hf + 1], pl_[ks][hf + 1]);
        }

        {
            unsigned vh[2][8], vl[2][8];
            LDB4(vh[0], vl[0], AS_VH, AS_VL, (lrow) * AP + 4 * lt);
#pragma unroll
            for (int nb = 0; nb < 8; nb++) {
                const int cur = nb & 1;
                if (nb < 7)
                    LDB4(vh[cur ^ 1], vl[cur ^ 1], AS_VH, AS_VL,
                         ((nb + 1) * 8 + lrow) * AP + 4 * lt);
#pragma unroll
                for (int ks = 0; ks < 4; ks++)
                    mma_bf16(O[nb], ph[ks], vh[cur][2 * ks], vh[cur][2 * ks + 1]);
#pragma unroll
                for (int ks = 0; ks < 4; ks++)
                    mma_bf16(O[nb], ph[ks], vl[cur][2 * ks], vl[cur][2 * ks + 1]);
#pragma unroll
                for (int ks = 0; ks < 4; ks++)
                    mma_bf16(O[nb], pl_[ks], vh[cur][2 * ks], vh[cur][2 * ks + 1]);
            }
        }
        stg = (stg + 1) % 3;
    }

    l0v += __shfl_xor_sync(0xffffffffu, l0v, 1);
    l0v += __shfl_xor_sync(0xffffffffu, l0v, 2);
    l1v += __shfl_xor_sync(0xffffffffu, l1v, 1);
    l1v += __shfl_xor_sync(0xffffffffu, l1v, 2);

    // Epilogue: CORRECTED pair-exchange. For each nb, lane tig owns cols
    // {2tig, 2tig+1}; its partner tig^1 owns the adjacent pair of the SAME nb.
    // Even tig stores nb0's quad, odd tig stores nb1's quad.
    const size_t prow = (size_t)(sp * 8 + b) * S_ + q0 + w * 16 + g;
#pragma unroll
    for (int np = 0; np < 4; np++) {
        const int nb0 = 2 * np, nb1 = nb0 + 1;
        float a0 = O[nb0][0], a1 = O[nb0][1];   // nb0, row g
        float b0 = O[nb0][2], b1 = O[nb0][3];   // nb0, row g+8
        float c0 = O[nb1][0], c1 = O[nb1][1];   // nb1, row g
        float d0 = O[nb1][2], d1 = O[nb1][3];   // nb1, row g+8
        float pa0 = __shfl_xor_sync(0xffffffffu, a0, 1);  // partner's nb0 vals
        float pa1 = __shfl_xor_sync(0xffffffffu, a1, 1);
        float pb0 = __shfl_xor_sync(0xffffffffu, b0, 1);
        float pb1 = __shfl_xor_sync(0xffffffffu, b1, 1);
        float pc0 = __shfl_xor_sync(0xffffffffu, c0, 1);  // partner's nb1 vals
        float pc1 = __shfl_xor_sync(0xffffffffu, c1, 1);
        float pd0 = __shfl_xor_sync(0xffffffffu, d0, 1);
        float pd1 = __shfl_xor_sync(0xffffffffu, d1, 1);
        if ((tig & 1) == 0) {
            // own cols 2tig,2tig+1; partner cols 2tig+2,2tig+3 (same nb0)
            const int d = nb0 * 8 + 2 * tig;               // 4-aligned (tig 0,2)
            *(float4*)&g_Op[prow * 64 + d]       = make_float4(a0, a1, pa0, pa1);
            *(float4*)&g_Op[(prow + 8) * 64 + d] = make_float4(b0, b1, pb0, pb1);
        } else {
            // partner (tig-1) cols 2tig-2,2tig-1; own cols 2tig,2tig+1 (nb1)
            const int d = nb1 * 8 + 2 * (tig ^ 1);         // 4-aligned
            *(float4*)&g_Op[prow * 64 + d]       = make_float4(pc0, pc1, c0, c1);
            *(float4*)&g_Op[(prow + 8) * 64 + d] = make_float4(pd0, pd1, d0, d1);
        }
    }
    if (tig == 0) {
        g_pl[prow] = l0v;
        g_pl[prow + 8] = l1v;
    }
}

// ---------------------------------------------------------------------------
// Combine the 4 KV splits. 2 float4 per thread (MLP ~12), grid 512x256.
// ---------------------------------------------------------------------------
__global__ __launch_bounds__(256) void combine_kernel(float* __restrict__ out)
{
    const int idx = blockIdx.x * 256 + threadIdx.x;   // 0..131071
    const int rg  = idx >> 3;                          // row
    const int j   = idx & 7;                           // float4 slot 0..7
    const size_t r0 = (size_t)rg * DK;
    const int cA = j * 4, cB = (j + 8) * 4;

    float4 a0 = *(const float4*)&g_Op[((size_t)0 * MTOT) * DK + r0 + cA];
    float4 b0 = *(const float4*)&g_Op[((size_t)0 * MTOT) * DK + r0 + cB];
    float4 a1 = *(const float4*)&g_Op[((size_t)1 * MTOT) * DK + r0 + cA];
    float4 b1 = *(const float4*)&g_Op[((size_t)1 * MTOT) * DK + r0 + cB];
    float4 a2 = *(const float4*)&g_Op[((size_t)2 * MTOT) * DK + r0 + cA];
    float4 b2 = *(const float4*)&g_Op[((size_t)2 * MTOT) * DK + r0 + cB];
    float4 a3 = *(const float4*)&g_Op[((size_t)3 * MTOT) * DK + r0 + cA];
    float4 b3 = *(const float4*)&g_Op[((size_t)3 * MTOT) * DK + r0 + cB];
    const float inv = 1.0f / (g_pl[rg] + g_pl[MTOT + rg] +
                              g_pl[2 * MTOT + rg] + g_pl[3 * MTOT + rg]);
    float4 ra, rb;
    ra.x = (a0.x + a1.x + a2.x + a3.x) * inv;
    ra.y = (a0.y + a1.y + a2.y + a3.y) * inv;
    ra.z = (a0.z + a1.z + a2.z + a3.z) * inv;
    ra.w = (a0.w + a1.w + a2.w + a3.w) * inv;
    rb.x = (b0.x + b1.x + b2.x + b3.x) * inv;
    rb.y = (b0.y + b1.y + b2.y + b3.y) * inv;
    rb.z = (b0.z + b1.z + b2.z + b3.z) * inv;
    rb.w = (b0.w + b1.w + b2.w + b3.w) * inv;
    *(float4*)&out[r0 + cA] = ra;
    *(float4*)&out[r0 + cB] = rb;
}

// ---------------------------------------------------------------------------
extern "C" void kernel_launch(void* const* d_in, const int* in_sizes, int n_in,
                              void* d_out, int out_size)
{
    const float* X  = (const float*)d_in[0];
    const float* Wq = (const float*)d_in[1];
    const float* Wk = (const float*)d_in[2];
    const float* Wv = (const float*)d_in[3];
    float* out = (float*)d_out;

    cvt_w_kernel<<<dim3(8, 3), 256>>>(Wq, Wk, Wv);

    const int qsm = 2 * QSTAGE * 4;   // 71680 B
    cudaFuncSetAttribute(qkv_mma_kernel,
                         cudaFuncAttributeMaxDynamicSharedMemorySize, qsm);
    qkv_mma_kernel<<<(MTOT / 128) * 2, 256, qsm>>>(X);

    const int asm_ = 3 * ASTAGE * 4;  // 110592 B
    cudaFuncSetAttribute(attn_kernel,
                         cudaFuncAttributeMaxDynamicSharedMemorySize, asm_);
    attn_kernel<<<8 * NSP * (S_ / 128), 256, asm_>>>();

    combine_kernel<<<MTOT * 8 / 256, 256>>>(out);
}

// round 16
// speedup vs baseline: 1.0129x; 1.0129x over previous
#include <cuda_runtime.h>
#include <cuda_bf16.h>
#include <math.h>

#define B_   8
#define S_   2048
#define DIN  1024
#define DK   64
#define MTOT (B_ * S_)
#define NFUS 192
#define NSP  4                     // split-KV factor

// bf16 hi/lo planes (u32 = 2 packed bf16 along contraction dim)
__device__ unsigned g_Whi[NFUS * DIN / 2], g_Wlo[NFUS * DIN / 2];   // [n][k/2]
__device__ unsigned g_Qhi[MTOT * 32], g_Qlo[MTOT * 32];             // x 0.125*log2(e)
__device__ unsigned g_Khi[MTOT * 32], g_Klo[MTOT * 32];
__device__ unsigned g_Vthi[B_ * 64 * 1024], g_Vtlo[B_ * 64 * 1024]; // [b][dim][kv/2]
// split-KV partials (max-free softmax)
__device__ float g_Op[NSP * MTOT * DK];
__device__ float g_pl[NSP * MTOT];

__device__ __forceinline__ unsigned pack_bf16(__nv_bfloat16 lo, __nv_bfloat16 hi)
{
    return (unsigned)__bfloat16_as_ushort(lo) |
           ((unsigned)__bfloat16_as_ushort(hi) << 16);
}
// hi/lo bf16 split of a float pair (RN, identical to __float2bfloat16).
__device__ __forceinline__ void split2(float a, float b, unsigned& hi, unsigned& lo)
{
    unsigned h;
    asm("cvt.rn.bf16x2.f32 %0, %1, %2;" : "=r"(h) : "f"(b), "f"(a));
    const float fa = __uint_as_float(h << 16);
    const float fb = __uint_as_float(h & 0xffff0000u);
    unsigned l;
    asm("cvt.rn.bf16x2.f32 %0, %1, %2;" : "=r"(l) : "f"(b - fb), "f"(a - fa));
    hi = h;
    lo = l;
}
__device__ __forceinline__ float ex2f(float x)
{
    float r;
    asm("ex2.approx.f32 %0, %1;" : "=f"(r) : "f"(x));
    return r;
}
__device__ __forceinline__ void mma_bf16(float c[4], const unsigned a[4],
                                         unsigned b0, unsigned b1)
{
    asm volatile(
        "mma.sync.aligned.m16n8k16.row.col.f32.bf16.bf16.f32 "
        "{%0,%1,%2,%3},{%4,%5,%6,%7},{%8,%9},{%0,%1,%2,%3};"
        : "+f"(c[0]), "+f"(c[1]), "+f"(c[2]), "+f"(c[3])
        : "r"(a[0]), "r"(a[1]), "r"(a[2]), "r"(a[3]), "r"(b0), "r"(b1));
}
__device__ __forceinline__ void ldm_x4(unsigned r[4], const unsigned* p)
{
    unsigned sa = (unsigned)__cvta_generic_to_shared(p);
    asm volatile("ldmatrix.sync.aligned.m8n8.x4.shared.b16 {%0,%1,%2,%3}, [%4];"
                 : "=r"(r[0]), "=r"(r[1]), "=r"(r[2]), "=r"(r[3]) : "r"(sa));
}
__device__ __forceinline__ void cp16(unsigned* smem_dst, const unsigned* gmem_src)
{
    unsigned sa = (unsigned)__cvta_generic_to_shared(smem_dst);
    asm volatile("cp.async.cg.shared.global [%0], [%1], 16;" :: "r"(sa), "l"(gmem_src));
}
#define CP_COMMIT() asm volatile("cp.async.commit_group;")
#define CP_WAIT0()  asm volatile("cp.async.wait_group 0;")
#define CP_WAIT1()  asm volatile("cp.async.wait_group 1;")

// ---------------------------------------------------------------------------
// W -> transposed bf16 hi/lo planes [192][1024]. Coalesced via smem transpose.
// ---------------------------------------------------------------------------
__global__ __launch_bounds__(256) void cvt_w_kernel(
    const float* __restrict__ Wq, const float* __restrict__ Wk,
    const float* __restrict__ Wv)
{
    __shared__ float sm[64 * 130];
    const int kblk = blockIdx.x;
    const int mat  = blockIdx.y;
    const float* Wsrc = (mat == 0) ? Wq : (mat == 1) ? Wk : Wv;
    const int t = threadIdx.x;

#pragma unroll
    for (int j = 0; j < 8; j++) {
        const int lin = j * 256 + t;
        const int r = lin >> 4, q = lin & 15;
        float4 v = *(const float4*)&Wsrc[(size_t)(kblk * 128 + r) * 64 + q * 4];
        sm[(q * 4 + 0) * 130 + r] = v.x;
        sm[(q * 4 + 1) * 130 + r] = v.y;
        sm[(q * 4 + 2) * 130 + r] = v.z;
        sm[(q * 4 + 3) * 130 + r] = v.w;
    }
    __syncthreads();

#pragma unroll
    for (int j = 0; j < 16; j++) {
        const int lin = j * 256 + t;
        const int n = lin >> 6, ku = lin & 63;
        unsigned hi, lo;
        split2(sm[n * 130 + 2 * ku], sm[n * 130 + 2 * ku + 1], hi, lo);
        const size_t o = (size_t)(mat * 64 + n) * 512 + kblk * 64 + ku;
        g_Whi[o] = hi;
        g_Wlo[o] = lo;
    }
}

// ---------------------------------------------------------------------------
// Pipelined bf16x3 QKV GEMM, fused X conversion, fused Vt transpose epilogue.
// CTA 128 rows x 96 cols, 256 thr (8 warps: wm 4 x wn 2, warp 32x48).
// ---------------------------------------------------------------------------
#define QP     20
#define QS_XH  0
#define QS_XL  (128 * QP)
#define QS_WH  (256 * QP)
#define QS_WL  (352 * QP)
#define QSTAGE (448 * QP)      // 8960 u32 = 35840 B

__global__ __launch_bounds__(256, 2) void qkv_mma_kernel(const float* __restrict__ X)
{
    extern __shared__ unsigned smq[];
    const int t    = threadIdx.x;
    const int lane = t & 31;
    const int w    = t >> 5;
    const int wm   = w & 3;
    const int wn   = w >> 2;
    const int g    = lane >> 2;
    const int tig  = lane & 3;
    const int m0   = (blockIdx.x >> 1) * 128;
    const int n0   = (blockIdx.x & 1) * 96;
    const int lrow = lane & 7;
    const int lt   = lane >> 3;

    float C[2][6][4];
#pragma unroll
    for (int a = 0; a < 2; a++)
#pragma unroll
        for (int b = 0; b < 6; b++)
#pragma unroll
            for (int c = 0; c < 4; c++) C[a][b][c] = 0.0f;

    float4 xreg[4];
    auto loadX = [&](int kc) {
#pragma unroll
        for (int j = 0; j < 4; j++) {
            const int lin = j * 256 + t;
            const int r = lin >> 3, q = lin & 7;
            xreg[j] = *(const float4*)&X[(size_t)(m0 + r) * DIN + kc * 32 + q * 4];
        }
    };
    auto stX = [&](int stg) {
        unsigned* dst = smq + stg * QSTAGE;
#pragma unroll
        for (int j = 0; j < 4; j++) {
            const int lin = j * 256 + t;
            const int r = lin >> 3, q = lin & 7;
            unsigned h0, l0, h1, l1;
            split2(xreg[j].x, xreg[j].y, h0, l0);
            split2(xreg[j].z, xreg[j].w, h1, l1);
            *(uint2*)&dst[QS_XH + r * QP + q * 2] = make_uint2(h0, h1);
            *(uint2*)&dst[QS_XL + r * QP + q * 2] = make_uint2(l0, l1);
        }
    };
    auto cpW = [&](int stg, int kc) {
        unsigned* dst = smq + stg * QSTAGE;
#pragma unroll
        for (int j = 0; j < 3; j++) {
            const int lin = j * 256 + t;
            const int plane = lin / 384, rem = lin - plane * 384;
            const int r = rem >> 2, sg = rem & 3;
            const unsigned* src = plane ? g_Wlo : g_Whi;
            cp16(dst + (plane ? QS_WL : QS_WH) + r * QP + sg * 4,
                 src + (size_t)(n0 + r) * 512 + kc * 16 + sg * 4);
        }
    };

    loadX(0);
    cpW(0, 0);
    CP_COMMIT();
    stX(0);
    CP_WAIT0();
    __syncthreads();

    for (int kc = 0; kc < 32; kc++) {
        const int stg = kc & 1;
        const unsigned* ST = smq + stg * QSTAGE;
        const bool more = (kc + 1 < 32);
        if (more) {
            loadX(kc + 1);
            cpW(stg ^ 1, kc + 1);
            CP_COMMIT();
        }

        unsigned aH[2][2][4], aL[2][2][4];
#pragma unroll
        for (int ks = 0; ks < 2; ks++)
#pragma unroll
            for (int mt = 0; mt < 2; mt++) {
                const int off = (wm * 32 + mt * 16 + (lt & 1) * 8 + lrow) * QP
                              + 8 * ks + 4 * (lt >> 1);
                ldm_x4(aH[ks][mt], ST + QS_XH + off);
                ldm_x4(aL[ks][mt], ST + QS_XL + off);
            }

        unsigned bh[2][4], bl[2][4];
        {
            const int b0 = (wn * 48 + lrow) * QP + 4 * lt;
            ldm_x4(bh[0], ST + QS_WH + b0);
            ldm_x4(bl[0], ST + QS_WL + b0);
        }
#pragma unroll
        for (int nt = 0; nt < 6; nt++) {
            const int cur = nt & 1;
            if (nt < 5) {
                const int bn = (wn * 48 + (nt + 1) * 8 + lrow) * QP + 4 * lt;
                ldm_x4(bh[cur ^ 1], ST + QS_WH + bn);
                ldm_x4(bl[cur ^ 1], ST + QS_WL + bn);
            }
#pragma unroll
            for (int ks = 0; ks < 2; ks++) {
                mma_bf16(C[0][nt], aH[ks][0], bh[cur][2 * ks], bh[cur][2 * ks + 1]);
                mma_bf16(C[1][nt], aH[ks][1], bh[cur][2 * ks], bh[cur][2 * ks + 1]);
                mma_bf16(C[0][nt], aH[ks][0], bl[cur][2 * ks], bl[cur][2 * ks + 1]);
                mma_bf16(C[1][nt], aH[ks][1], bl[cur][2 * ks], bl[cur][2 * ks + 1]);
                mma_bf16(C[0][nt], aL[ks][0], bh[cur][2 * ks], bh[cur][2 * ks + 1]);
                mma_bf16(C[1][nt], aL[ks][1], bh[cur][2 * ks], bh[cur][2 * ks + 1]);
            }
        }

        if (more) {
            stX(stg ^ 1);
            CP_WAIT0();
        }
        __syncthreads();
    }

    // Epilogue: Q x 0.125*log2e; K planes; V transposed to g_Vt (fused).
    __nv_bfloat16* vs_h = (__nv_bfloat16*)smq;          // [64][130]
    __nv_bfloat16* vs_l = vs_h + 64 * 130;

#pragma unroll
    for (int nt = 0; nt < 6; nt++) {
        const int col = n0 + wn * 48 + nt * 8 + tig * 2;
        const int mat = col >> 6;
        if (mat < 2) {
            const int idx = (col & 63) >> 1;
            unsigned* dhi = (mat == 0) ? g_Qhi : g_Khi;
            unsigned* dlo = (mat == 0) ? g_Qlo : g_Klo;
            const float sc = (mat == 0) ? 0.18033688f : 1.0f;  // 0.125*log2(e)
#pragma unroll
            for (int mt = 0; mt < 2; mt++) {
                const int row = m0 + wm * 32 + mt * 16 + g;
                unsigned hi, lo;
                split2(C[mt][nt][0] * sc, C[mt][nt][1] * sc, hi, lo);
                dhi[(size_t)row * 32 + idx] = hi;
                dlo[(size_t)row * 32 + idx] = lo;
                split2(C[mt][nt][2] * sc, C[mt][nt][3] * sc, hi, lo);
                dhi[(size_t)(row + 8) * 32 + idx] = hi;
                dlo[(size_t)(row + 8) * 32 + idx] = lo;
            }
        } else {
            const int d = col & 63;
#pragma unroll
            for (int mt = 0; mt < 2; mt++) {
                const int r = wm * 32 + mt * 16 + g;
                unsigned hi, lo;
                split2(C[mt][nt][0], C[mt][nt][1], hi, lo);
                vs_h[d * 130 + r]       = __ushort_as_bfloat16((unsigned short)(hi & 0xffff));
                vs_h[(d + 1) * 130 + r] = __ushort_as_bfloat16((unsigned short)(hi >> 16));
                vs_l[d * 130 + r]       = __ushort_as_bfloat16((unsigned short)(lo & 0xffff));
                vs_l[(d + 1) * 130 + r] = __ushort_as_bfloat16((unsigned short)(lo >> 16));
                split2(C[mt][nt][2], C[mt][nt][3], hi, lo);
                vs_h[d * 130 + r + 8]       = __ushort_as_bfloat16((unsigned short)(hi & 0xffff));
                vs_h[(d + 1) * 130 + r + 8] = __ushort_as_bfloat16((unsigned short)(hi >> 16));
                vs_l[d * 130 + r + 8]       = __ushort_as_bfloat16((unsigned short)(lo & 0xffff));
                vs_l[(d + 1) * 130 + r + 8] = __ushort_as_bfloat16((unsigned short)(lo >> 16));
            }
        }
    }
    __syncthreads();

    if (n0 == 96) {
        const int b   = m0 >> 11;
        const int kvb = (m0 & 2047) >> 1;
#pragma unroll
        for (int i = 0; i < 32; i++) {
            const int lin = i * 256 + t;
            const int plane = lin >> 12;
            const int rem = lin & 4095;
            const int d = rem >> 6, j = rem & 63;
            const __nv_bfloat16* src = plane ? vs_l : vs_h;
            unsigned v = pack_bf16(src[d * 130 + 2 * j], src[d * 130 + 2 * j + 1]);
            (plane ? g_Vtlo : g_Vthi)[(size_t)(b * 64 + d) * 1024 + kvb + j] = v;
        }
    }
}

// ---------------------------------------------------------------------------
// Pipelined HMMA flash attention, causal, 4-way split-KV, max-free exp2
// softmax. CTA = 128 q-rows, 256 thr. Grid 512. 3-stage cp.async pipeline.
// ---------------------------------------------------------------------------
#define AP     36
#define AS_KH  0
#define AS_KL  (64 * AP)
#define AS_VH  (128 * AP)
#define AS_VL  (192 * AP)
#define ASTAGE (256 * AP)     // 9216 u32 = 36 KB

#define LDB4(H, L, HOFF, LOFF, base) do {          \
    ldm_x4(H,     ST + (HOFF) + (base));           \
    ldm_x4((H) + 4, ST + (HOFF) + (base) + 16);    \
    ldm_x4(L,     ST + (LOFF) + (base));           \
    ldm_x4((L) + 4, ST + (LOFF) + (base) + 16);    \
} while (0)

__global__ __launch_bounds__(256, 2) void attn_kernel()
{
    extern __shared__ unsigned sma[];
    const int bx = blockIdx.x;
    const int b  = bx & 7;
    const int sp = (bx >> 3) & 3;
    const int qt = 15 - (bx >> 5);
    const int t  = threadIdx.x;
    const int lane = t & 31;
    const int w    = t >> 5;
    const int g    = lane >> 2;
    const int tig  = lane & 3;
    const int q0 = qt * 128;
    const int lrow = lane & 7;
    const int lt   = lane >> 3;

    const int rowg  = q0 + w * 16 + g;
    const int grow0 = b * S_ + rowg;
    const int last  = 2 * qt + 1;
    const int ntile = (last >= sp) ? ((last - sp) >> 2) + 1 : 0;

    unsigned qh[4][4], ql[4][4];
#pragma unroll
    for (int ks = 0; ks < 4; ks++) {
        const int i0 = 8 * ks + tig;
        qh[ks][0] = g_Qhi[(size_t)grow0 * 32 + i0];
        qh[ks][1] = g_Qhi[(size_t)(grow0 + 8) * 32 + i0];
        qh[ks][2] = g_Qhi[(size_t)grow0 * 32 + i0 + 4];
        qh[ks][3] = g_Qhi[(size_t)(grow0 + 8) * 32 + i0 + 4];
        ql[ks][0] = g_Qlo[(size_t)grow0 * 32 + i0];
        ql[ks][1] = g_Qlo[(size_t)(grow0 + 8) * 32 + i0];
        ql[ks][2] = g_Qlo[(size_t)grow0 * 32 + i0 + 4];
        ql[ks][3] = g_Qlo[(size_t)(grow0 + 8) * 32 + i0 + 4];
    }

    float O[8][4];
#pragma unroll
    for (int nb = 0; nb < 8; nb++)
#pragma unroll
        for (int c = 0; c < 4; c++) O[nb][c] = 0.0f;
    float l0v = 0.0f, l1v = 0.0f;

    auto fillA = [&](int stg, int kt) {
        unsigned* dst = sma + stg * ASTAGE;
#pragma unroll
        for (int j = 0; j < 8; j++) {
            const int lin = j * 256 + t;
            const int pl  = lin >> 9;
            const int rem = lin & 511;
            const int r = rem >> 3, sg = rem & 7;
            const unsigned* src;
            size_t off;
            int doff;
            if (pl < 2) {
                src = pl ? g_Klo : g_Khi;
                off = (size_t)(b * 2048 + kt * 64 + r) * 32 + sg * 4;
                doff = pl ? AS_KL : AS_KH;
            } else {
                src = (pl == 3) ? g_Vtlo : g_Vthi;
                off = (size_t)(b * 64 + r) * 1024 + kt * 32 + sg * 4;
                doff = (pl == 3) ? AS_VL : AS_VH;
            }
            cp16(dst + doff + r * AP + sg * 4, src + off);
        }
    };

    if (ntile > 0) { fillA(0, sp);     CP_COMMIT(); }
    if (ntile > 1) { fillA(1, sp + 4); CP_COMMIT(); }

    int stg = 0;
    for (int it = 0; it < ntile; it++) {
        const int kt = sp + it * 4;
        if (it == ntile - 1) { CP_WAIT0(); } else { CP_WAIT1(); }
        __syncthreads();
        if (it + 2 < ntile) {
            fillA((stg + 2) % 3, kt + 8);
            CP_COMMIT();
        }
        const unsigned* ST = sma + stg * ASTAGE;

        float S[8][4];
#pragma unroll
        for (int nb = 0; nb < 8; nb++)
#pragma unroll
            for (int c = 0; c < 4; c++) S[nb][c] = 0.0f;

        {
            unsigned kh[2][8], kl[2][8];
            LDB4(kh[0], kl[0], AS_KH, AS_KL, (lrow) * AP + 4 * lt);
#pragma unroll
            for (int nb = 0; nb < 8; nb++) {
                const int cur = nb & 1;
                if (nb < 7)
                    LDB4(kh[cur ^ 1], kl[cur ^ 1], AS_KH, AS_KL,
                         ((nb + 1) * 8 + lrow) * AP + 4 * lt);
#pragma unroll
                for (int ks = 0; ks < 4; ks++)
                    mma_bf16(S[nb], qh[ks], kh[cur][2 * ks], kh[cur][2 * ks + 1]);
#pragma unroll
                for (int ks = 0; ks < 4; ks++)
                    mma_bf16(S[nb], qh[ks], kl[cur][2 * ks], kl[cur][2 * ks + 1]);
#pragma unroll
                for (int ks = 0; ks < 4; ks++)
                    mma_bf16(S[nb], ql[ks], kh[cur][2 * ks], kh[cur][2 * ks + 1]);
            }
        }

        if (kt * 64 + 63 > rowg) {
#pragma unroll
            for (int nb = 0; nb < 8; nb++) {
                const int c0 = kt * 64 + nb * 8 + 2 * tig;
                if (c0 > rowg)         S[nb][0] = -INFINITY;
                if (c0 + 1 > rowg)     S[nb][1] = -INFINITY;
                if (c0 > rowg + 8)     S[nb][2] = -INFINITY;
                if (c0 + 1 > rowg + 8) S[nb][3] = -INFINITY;
            }
        }

        unsigned ph[4][4], pl_[4][4];
#pragma unroll
        for (int nb = 0; nb < 8; nb++) {
            const float p00 = ex2f(S[nb][0]);
            const float p01 = ex2f(S[nb][1]);
            const float p10 = ex2f(S[nb][2]);
            const float p11 = ex2f(S[nb][3]);
            l0v += p00 + p01;
            l1v += p10 + p11;
            const int ks = nb >> 1;
            const int hf = (nb & 1) * 2;
            split2(p00, p01, ph[ks][hf + 0], pl_[ks][hf + 0]);
            split2(p10, p11, ph[ks][hf + 1], pl_[ks][hf + 1]);
        }

        {
            unsigned vh[2][8], vl[2][8];
            LDB4(vh[0], vl[0], AS_VH, AS_VL, (lrow) * AP + 4 * lt);
#pragma unroll
            for (int nb = 0; nb < 8; nb++) {
                const int cur = nb & 1;
                if (nb < 7)
                    LDB4(vh[cur ^ 1], vl[cur ^ 1], AS_VH, AS_VL,
                         ((nb + 1) * 8 + lrow) * AP + 4 * lt);
#pragma unroll
                for (int ks = 0; ks < 4; ks++)
                    mma_bf16(O[nb], ph[ks], vh[cur][2 * ks], vh[cur][2 * ks + 1]);
#pragma unroll
                for (int ks = 0; ks < 4; ks++)
                    mma_bf16(O[nb], ph[ks], vl[cur][2 * ks], vl[cur][2 * ks + 1]);
#pragma unroll
                for (int ks = 0; ks < 4; ks++)
                    mma_bf16(O[nb], pl_[ks], vh[cur][2 * ks], vh[cur][2 * ks + 1]);
            }
        }
        stg = (stg + 1) % 3;
    }

    l0v += __shfl_xor_sync(0xffffffffu, l0v, 1);
    l0v += __shfl_xor_sync(0xffffffffu, l0v, 2);
    l1v += __shfl_xor_sync(0xffffffffu, l1v, 1);
    l1v += __shfl_xor_sync(0xffffffffu, l1v, 2);

    const size_t prow = (size_t)(sp * 8 + b) * S_ + q0 + w * 16 + g;
#pragma unroll
    for (int nb = 0; nb < 8; nb++) {
        const int d = nb * 8 + 2 * tig;
        *(float2*)&g_Op[prow * 64 + d]       = make_float2(O[nb][0], O[nb][1]);
        *(float2*)&g_Op[(prow + 8) * 64 + d] = make_float2(O[nb][2], O[nb][3]);
    }
    if (tig == 0) {
        g_pl[prow] = l0v;
        g_pl[prow + 8] = l1v;
    }
}

// ---------------------------------------------------------------------------
// Combine the 4 KV splits. One float4 per thread, grid 1024x256 -> MLP 4.
// ---------------------------------------------------------------------------
__global__ __launch_bounds__(256) void combine_kernel(float* __restrict__ out)
{
    const int idx = blockIdx.x * 256 + threadIdx.x;   // 0..262143
    const int rg  = idx >> 4;                          // row
    const int c   = (idx & 15) * 4;                    // col offset
    float4 o0 = *(const float4*)&g_Op[((size_t)0 * MTOT + rg) * DK + c];
    float4 o1 = *(const float4*)&g_Op[((size_t)1 * MTOT + rg) * DK + c];
    float4 o2 = *(const float4*)&g_Op[((size_t)2 * MTOT + rg) * DK + c];
    float4 o3 = *(const float4*)&g_Op[((size_t)3 * MTOT + rg) * DK + c];
    const float inv = 1.0f / (g_pl[rg] + g_pl[MTOT + rg] +
                              g_pl[2 * MTOT + rg] + g_pl[3 * MTOT + rg]);
    float4 r;
    r.x = (o0.x + o1.x + o2.x + o3.x) * inv;
    r.y = (o0.y + o1.y + o2.y + o3.y) * inv;
    r.z = (o0.z + o1.z + o2.z + o3.z) * inv;
    r.w = (o0.w + o1.w + o2.w + o3.w) * inv;
    *(float4*)&out[(size_t)rg * DK + c] = r;
}

// ---------------------------------------------------------------------------
extern "C" void kernel_launch(void* const* d_in, const int* in_sizes, int n_in,
                              void* d_out, int out_size)
{
    const float* X  = (const float*)d_in[0];
    const float* Wq = (const float*)d_in[1];
    const float* Wk = (const float*)d_in[2];
    const float* Wv = (const float*)d_in[3];
    float* out = (float*)d_out;

    cvt_w_kernel<<<dim3(8, 3), 256>>>(Wq, Wk, Wv);

    const int qsm = 2 * QSTAGE * 4;   // 71680 B
    cudaFuncSetAttribute(qkv_mma_kernel,
                         cudaFuncAttributeMaxDynamicSharedMemorySize, qsm);
    qkv_mma_kernel<<<(MTOT / 128) * 2, 256, qsm>>>(X);

    const int asm_ = 3 * ASTAGE * 4;  // 110592 B
    cudaFuncSetAttribute(attn_kernel,
                         cudaFuncAttributeMaxDynamicSharedMemorySize, asm_);
    attn_kernel<<<8 * NSP * (S_ / 128), 256, asm_>>>();

    combine_kernel<<<MTOT * DK / 4 / 256, 256>>>(out);
}

// round 17
// speedup vs baseline: 1.0140x; 1.0011x over previous
#include <cuda_runtime.h>
#include <cuda_bf16.h>
#include <math.h>

#define B_   8
#define S_   2048
#define DIN  1024
#define DK   64
#define MTOT (B_ * S_)
#define NFUS 192
#define NSP  4                     // split-KV factor

// bf16 hi/lo planes (u32 = 2 packed bf16 along contraction dim)
__device__ unsigned g_Whi[NFUS * DIN / 2], g_Wlo[NFUS * DIN / 2];   // [n][k/2]
__device__ unsigned g_Qhi[MTOT * 32], g_Qlo[MTOT * 32];             // x 0.125*log2(e)
__device__ unsigned g_Khi[MTOT * 32], g_Klo[MTOT * 32];
__device__ unsigned g_Vthi[B_ * 64 * 1024], g_Vtlo[B_ * 64 * 1024]; // [b][dim][kv/2]
// split-KV partials (max-free softmax)
__device__ float g_Op[NSP * MTOT * DK];
__device__ float g_pl[NSP * MTOT];

__device__ __forceinline__ unsigned pack_bf16(__nv_bfloat16 lo, __nv_bfloat16 hi)
{
    return (unsigned)__bfloat16_as_ushort(lo) |
           ((unsigned)__bfloat16_as_ushort(hi) << 16);
}
// hi/lo bf16 split of a float pair (RN, identical to __float2bfloat16).
__device__ __forceinline__ void split2(float a, float b, unsigned& hi, unsigned& lo)
{
    unsigned h;
    asm("cvt.rn.bf16x2.f32 %0, %1, %2;" : "=r"(h) : "f"(b), "f"(a));
    const float fa = __uint_as_float(h << 16);
    const float fb = __uint_as_float(h & 0xffff0000u);
    unsigned l;
    asm("cvt.rn.bf16x2.f32 %0, %1, %2;" : "=r"(l) : "f"(b - fb), "f"(a - fa));
    hi = h;
    lo = l;
}
__device__ __forceinline__ float ex2f(float x)
{
    float r;
    asm("ex2.approx.f32 %0, %1;" : "=f"(r) : "f"(x));
    return r;
}
__device__ __forceinline__ void mma_bf16(float c[4], const unsigned a[4],
                                         unsigned b0, unsigned b1)
{
    asm volatile(
        "mma.sync.aligned.m16n8k16.row.col.f32.bf16.bf16.f32 "
        "{%0,%1,%2,%3},{%4,%5,%6,%7},{%8,%9},{%0,%1,%2,%3};"
        : "+f"(c[0]), "+f"(c[1]), "+f"(c[2]), "+f"(c[3])
        : "r"(a[0]), "r"(a[1]), "r"(a[2]), "r"(a[3]), "r"(b0), "r"(b1));
}
__device__ __forceinline__ void ldm_x4(unsigned r[4], const unsigned* p)
{
    unsigned sa = (unsigned)__cvta_generic_to_shared(p);
    asm volatile("ldmatrix.sync.aligned.m8n8.x4.shared.b16 {%0,%1,%2,%3}, [%4];"
                 : "=r"(r[0]), "=r"(r[1]), "=r"(r[2]), "=r"(r[3]) : "r"(sa));
}
__device__ __forceinline__ void cp16(unsigned* smem_dst, const unsigned* gmem_src)
{
    unsigned sa = (unsigned)__cvta_generic_to_shared(smem_dst);
    asm volatile("cp.async.cg.shared.global [%0], [%1], 16;" :: "r"(sa), "l"(gmem_src));
}
#define CP_COMMIT() asm volatile("cp.async.commit_group;")
#define CP_WAIT0()  asm volatile("cp.async.wait_group 0;")
#define CP_WAIT1()  asm volatile("cp.async.wait_group 1;")

// ---------------------------------------------------------------------------
// W -> transposed bf16 hi/lo planes [192][1024]. Coalesced via smem transpose.
// ---------------------------------------------------------------------------
__global__ __launch_bounds__(256) void cvt_w_kernel(
    const float* __restrict__ Wq, const float* __restrict__ Wk,
    const float* __restrict__ Wv)
{
    __shared__ float sm[64 * 130];
    const int kblk = blockIdx.x;
    const int mat  = blockIdx.y;
    const float* Wsrc = (mat == 0) ? Wq : (mat == 1) ? Wk : Wv;
    const int t = threadIdx.x;

#pragma unroll
    for (int j = 0; j < 8; j++) {
        const int lin = j * 256 + t;
        const int r = lin >> 4, q = lin & 15;
        float4 v = *(const float4*)&Wsrc[(size_t)(kblk * 128 + r) * 64 + q * 4];
        sm[(q * 4 + 0) * 130 + r] = v.x;
        sm[(q * 4 + 1) * 130 + r] = v.y;
        sm[(q * 4 + 2) * 130 + r] = v.z;
        sm[(q * 4 + 3) * 130 + r] = v.w;
    }
    __syncthreads();

#pragma unroll
    for (int j = 0; j < 16; j++) {
        const int lin = j * 256 + t;
        const int n = lin >> 6, ku = lin & 63;
        unsigned hi, lo;
        split2(sm[n * 130 + 2 * ku], sm[n * 130 + 2 * ku + 1], hi, lo);
        const size_t o = (size_t)(mat * 64 + n) * 512 + kblk * 64 + ku;
        g_Whi[o] = hi;
        g_Wlo[o] = lo;
    }
}

// ---------------------------------------------------------------------------
// Pipelined bf16x3 QKV GEMM, fused X conversion, fused Vt transpose epilogue.
// CTA 128 rows x 96 cols, 256 thr (8 warps: wm 4 x wn 2, warp 32x48).
// Inner loop: nt-pairs, term-major, 4-accumulator rotation (same-acc
// spacing 4) — the R10-measured structure.
// ---------------------------------------------------------------------------
#define QP     20
#define QS_XH  0
#define QS_XL  (128 * QP)
#define QS_WH  (256 * QP)
#define QS_WL  (352 * QP)
#define QSTAGE (448 * QP)      // 8960 u32 = 35840 B

__global__ __launch_bounds__(256, 2) void qkv_mma_kernel(const float* __restrict__ X)
{
    extern __shared__ unsigned smq[];
    const int t    = threadIdx.x;
    const int lane = t & 31;
    const int w    = t >> 5;
    const int wm   = w & 3;
    const int wn   = w >> 2;
    const int g    = lane >> 2;
    const int tig  = lane & 3;
    const int m0   = (blockIdx.x >> 1) * 128;
    const int n0   = (blockIdx.x & 1) * 96;
    const int lrow = lane & 7;
    const int lt   = lane >> 3;

    float C[2][6][4];
#pragma unroll
    for (int a = 0; a < 2; a++)
#pragma unroll
        for (int b = 0; b < 6; b++)
#pragma unroll
            for (int c = 0; c < 4; c++) C[a][b][c] = 0.0f;

    float4 xreg[4];
    auto loadX = [&](int kc) {
#pragma unroll
        for (int j = 0; j < 4; j++) {
            const int lin = j * 256 + t;
            const int r = lin >> 3, q = lin & 7;
            xreg[j] = *(const float4*)&X[(size_t)(m0 + r) * DIN + kc * 32 + q * 4];
        }
    };
    auto stX = [&](int stg) {
        unsigned* dst = smq + stg * QSTAGE;
#pragma unroll
        for (int j = 0; j < 4; j++) {
            const int lin = j * 256 + t;
            const int r = lin >> 3, q = lin & 7;
            unsigned h0, l0, h1, l1;
            split2(xreg[j].x, xreg[j].y, h0, l0);
            split2(xreg[j].z, xreg[j].w, h1, l1);
            *(uint2*)&dst[QS_XH + r * QP + q * 2] = make_uint2(h0, h1);
            *(uint2*)&dst[QS_XL + r * QP + q * 2] = make_uint2(l0, l1);
        }
    };
    auto cpW = [&](int stg, int kc) {
        unsigned* dst = smq + stg * QSTAGE;
#pragma unroll
        for (int j = 0; j < 3; j++) {
            const int lin = j * 256 + t;
            const int plane = lin / 384, rem = lin - plane * 384;
            const int r = rem >> 2, sg = rem & 3;
            const unsigned* src = plane ? g_Wlo : g_Whi;
            cp16(dst + (plane ? QS_WL : QS_WH) + r * QP + sg * 4,
                 src + (size_t)(n0 + r) * 512 + kc * 16 + sg * 4);
        }
    };

    loadX(0);
    cpW(0, 0);
    CP_COMMIT();
    stX(0);
    CP_WAIT0();
    __syncthreads();

    for (int kc = 0; kc < 32; kc++) {
        const int stg = kc & 1;
        const unsigned* ST = smq + stg * QSTAGE;
        const bool more = (kc + 1 < 32);
        if (more) {
            loadX(kc + 1);
            cpW(stg ^ 1, kc + 1);
            CP_COMMIT();
        }

        unsigned aH[2][2][4], aL[2][2][4];
#pragma unroll
        for (int ks = 0; ks < 2; ks++)
#pragma unroll
            for (int mt = 0; mt < 2; mt++) {
                const int off = (wm * 32 + mt * 16 + (lt & 1) * 8 + lrow) * QP
                              + 8 * ks + 4 * (lt >> 1);
                ldm_x4(aH[ks][mt], ST + QS_XH + off);
                ldm_x4(aL[ks][mt], ST + QS_XL + off);
            }

        // nt-pairs + term-major: 4 accumulators in rotation (spacing 4).
#pragma unroll
        for (int np = 0; np < 3; np++) {
            const int nt0 = 2 * np, nt1 = nt0 + 1;
            const int b0off = (wn * 48 + nt0 * 8 + lrow) * QP + 4 * lt;
            const int b1off = (wn * 48 + nt1 * 8 + lrow) * QP + 4 * lt;
            unsigned b0H[4], b0L[4], b1H[4], b1L[4];
            ldm_x4(b0H, ST + QS_WH + b0off);
            ldm_x4(b0L, ST + QS_WL + b0off);
            ldm_x4(b1H, ST + QS_WH + b1off);
            ldm_x4(b1L, ST + QS_WL + b1off);
#pragma unroll
            for (int ks = 0; ks < 2; ks++) {
                // term HH
                mma_bf16(C[0][nt0], aH[ks][0], b0H[2 * ks], b0H[2 * ks + 1]);
                mma_bf16(C[0][nt1], aH[ks][0], b1H[2 * ks], b1H[2 * ks + 1]);
                mma_bf16(C[1][nt0], aH[ks][1], b0H[2 * ks], b0H[2 * ks + 1]);
                mma_bf16(C[1][nt1], aH[ks][1], b1H[2 * ks], b1H[2 * ks + 1]);
                // term HL
                mma_bf16(C[0][nt0], aH[ks][0], b0L[2 * ks], b0L[2 * ks + 1]);
                mma_bf16(C[0][nt1], aH[ks][0], b1L[2 * ks], b1L[2 * ks + 1]);
                mma_bf16(C[1][nt0], aH[ks][1], b0L[2 * ks], b0L[2 * ks + 1]);
                mma_bf16(C[1][nt1], aH[ks][1], b1L[2 * ks], b1L[2 * ks + 1]);
                // term LH
                mma_bf16(C[0][nt0], aL[ks][0], b0H[2 * ks], b0H[2 * ks + 1]);
                mma_bf16(C[0][nt1], aL[ks][0], b1H[2 * ks], b1H[2 * ks + 1]);
                mma_bf16(C[1][nt0], aL[ks][1], b0H[2 * ks], b0H[2 * ks + 1]);
                mma_bf16(C[1][nt1], aL[ks][1], b1H[2 * ks], b1H[2 * ks + 1]);
            }
        }

        if (more) {
            stX(stg ^ 1);
            CP_WAIT0();
        }
        __syncthreads();
    }

    // Epilogue: Q x 0.125*log2e; K planes; V transposed to g_Vt (fused).
    __nv_bfloat16* vs_h = (__nv_bfloat16*)smq;          // [64][130]
    __nv_bfloat16* vs_l = vs_h + 64 * 130;

#pragma unroll
    for (int nt = 0; nt < 6; nt++) {
        const int col = n0 + wn * 48 + nt * 8 + tig * 2;
        const int mat = col >> 6;
        if (mat < 2) {
            const int idx = (col & 63) >> 1;
            unsigned* dhi = (mat == 0) ? g_Qhi : g_Khi;
            unsigned* dlo = (mat == 0) ? g_Qlo : g_Klo;
            const float sc = (mat == 0) ? 0.18033688f : 1.0f;  // 0.125*log2(e)
#pragma unroll
            for (int mt = 0; mt < 2; mt++) {
                const int row = m0 + wm * 32 + mt * 16 + g;
                unsigned hi, lo;
                split2(C[mt][nt][0] * sc, C[mt][nt][1] * sc, hi, lo);
                dhi[(size_t)row * 32 + idx] = hi;
                dlo[(size_t)row * 32 + idx] = lo;
                split2(C[mt][nt][2] * sc, C[mt][nt][3] * sc, hi, lo);
                dhi[(size_t)(row + 8) * 32 + idx] = hi;
                dlo[(size_t)(row + 8) * 32 + idx] = lo;
            }
        } else {
            const int d = col & 63;
#pragma unroll
            for (int mt = 0; mt < 2; mt++) {
                const int r = wm * 32 + mt * 16 + g;
                unsigned hi, lo;
                split2(C[mt][nt][0], C[mt][nt][1], hi, lo);
                vs_h[d * 130 + r]       = __ushort_as_bfloat16((unsigned short)(hi & 0xffff));
                vs_h[(d + 1) * 130 + r] = __ushort_as_bfloat16((unsigned short)(hi >> 16));
                vs_l[d * 130 + r]       = __ushort_as_bfloat16((unsigned short)(lo & 0xffff));
                vs_l[(d + 1) * 130 + r] = __ushort_as_bfloat16((unsigned short)(lo >> 16));
                split2(C[mt][nt][2], C[mt][nt][3], hi, lo);
                vs_h[d * 130 + r + 8]       = __ushort_as_bfloat16((unsigned short)(hi & 0xffff));
                vs_h[(d + 1) * 130 + r + 8] = __ushort_as_bfloat16((unsigned short)(hi >> 16));
                vs_l[d * 130 + r + 8]       = __ushort_as_bfloat16((unsigned short)(lo & 0xffff));
                vs_l[(d + 1) * 130 + r + 8] = __ushort_as_bfloat16((unsigned short)(lo >> 16));
            }
        }
    }
    __syncthreads();

    if (n0 == 96) {
        const int b   = m0 >> 11;
        const int kvb = (m0 & 2047) >> 1;
#pragma unroll
        for (int i = 0; i < 32; i++) {
            const int lin = i * 256 + t;
            const int plane = lin >> 12;
            const int rem = lin & 4095;
            const int d = rem >> 6, j = rem & 63;
            const __nv_bfloat16* src = plane ? vs_l : vs_h;
            unsigned v = pack_bf16(src[d * 130 + 2 * j], src[d * 130 + 2 * j + 1]);
            (plane ? g_Vtlo : g_Vthi)[(size_t)(b * 64 + d) * 1024 + kvb + j] = v;
        }
    }
}

// ---------------------------------------------------------------------------
// Pipelined HMMA flash attention, causal, 4-way split-KV, max-free exp2
// softmax. CTA = 128 q-rows, 256 thr. Grid 512. 3-stage cp.async pipeline.
// ---------------------------------------------------------------------------
#define AP     36
#define AS_KH  0
#define AS_KL  (64 * AP)
#define AS_VH  (128 * AP)
#define AS_VL  (192 * AP)
#define ASTAGE (256 * AP)     // 9216 u32 = 36 KB

#define LDB4(H, L, HOFF, LOFF, base) do {          \
    ldm_x4(H,     ST + (HOFF) + (base));           \
    ldm_x4((H) + 4, ST + (HOFF) + (base) + 16);    \
    ldm_x4(L,     ST + (LOFF) + (base));           \
    ldm_x4((L) + 4, ST + (LOFF) + (base) + 16);    \
} while (0)

__global__ __launch_bounds__(256, 2) void attn_kernel()
{
    extern __shared__ unsigned sma[];
    const int bx = blockIdx.x;
    const int b  = bx & 7;
    const int sp = (bx >> 3) & 3;
    const int qt = 15 - (bx >> 5);
    const int t  = threadIdx.x;
    const int lane = t & 31;
    const int w    = t >> 5;
    const int g    = lane >> 2;
    const int tig  = lane & 3;
    const int q0 = qt * 128;
    const int lrow = lane & 7;
    const int lt   = lane >> 3;

    const int rowg  = q0 + w * 16 + g;
    const int grow0 = b * S_ + rowg;
    const int last  = 2 * qt + 1;
    const int ntile = (last >= sp) ? ((last - sp) >> 2) + 1 : 0;

    unsigned qh[4][4], ql[4][4];
#pragma unroll
    for (int ks = 0; ks < 4; ks++) {
        const int i0 = 8 * ks + tig;
        qh[ks][0] = g_Qhi[(size_t)grow0 * 32 + i0];
        qh[ks][1] = g_Qhi[(size_t)(grow0 + 8) * 32 + i0];
        qh[ks][2] = g_Qhi[(size_t)grow0 * 32 + i0 + 4];
        qh[ks][3] = g_Qhi[(size_t)(grow0 + 8) * 32 + i0 + 4];
        ql[ks][0] = g_Qlo[(size_t)grow0 * 32 + i0];
        ql[ks][1] = g_Qlo[(size_t)(grow0 + 8) * 32 + i0];
        ql[ks][2] = g_Qlo[(size_t)grow0 * 32 + i0 + 4];
        ql[ks][3] = g_Qlo[(size_t)(grow0 + 8) * 32 + i0 + 4];
    }

    float O[8][4];
#pragma unroll
    for (int nb = 0; nb < 8; nb++)
#pragma unroll
        for (int c = 0; c < 4; c++) O[nb][c] = 0.0f;
    float l0v = 0.0f, l1v = 0.0f;

    auto fillA = [&](int stg, int kt) {
        unsigned* dst = sma + stg * ASTAGE;
#pragma unroll
        for (int j = 0; j < 8; j++) {
            const int lin = j * 256 + t;
            const int pl  = lin >> 9;
            const int rem = lin & 511;
            const int r = rem >> 3, sg = rem & 7;
            const unsigned* src;
            size_t off;
            int doff;
            if (pl < 2) {
                src = pl ? g_Klo : g_Khi;
                off = (size_t)(b * 2048 + kt * 64 + r) * 32 + sg * 4;
                doff = pl ? AS_KL : AS_KH;
            } else {
                src = (pl == 3) ? g_Vtlo : g_Vthi;
                off = (size_t)(b * 64 + r) * 1024 + kt * 32 + sg * 4;
                doff = (pl == 3) ? AS_VL : AS_VH;
            }
            cp16(dst + doff + r * AP + sg * 4, src + off);
        }
    };

    if (ntile > 0) { fillA(0, sp);     CP_COMMIT(); }
    if (ntile > 1) { fillA(1, sp + 4); CP_COMMIT(); }

    int stg = 0;
    for (int it = 0; it < ntile; it++) {
        const int kt = sp + it * 4;
        if (it == ntile - 1) { CP_WAIT0(); } else { CP_WAIT1(); }
        __syncthreads();
        if (it + 2 < ntile) {
            fillA((stg + 2) % 3, kt + 8);
            CP_COMMIT();
        }
        const unsigned* ST = sma + stg * ASTAGE;

        float S[8][4];
#pragma unroll
        for (int nb = 0; nb < 8; nb++)
#pragma unroll
            for (int c = 0; c < 4; c++) S[nb][c] = 0.0f;

        {
            unsigned kh[2][8], kl[2][8];
            LDB4(kh[0], kl[0], AS_KH, AS_KL, (lrow) * AP + 4 * lt);
#pragma unroll
            for (int nb = 0; nb < 8; nb++) {
                const int cur = nb & 1;
                if (nb < 7)
                    LDB4(kh[cur ^ 1], kl[cur ^ 1], AS_KH, AS_KL,
                         ((nb + 1) * 8 + lrow) * AP + 4 * lt);
#pragma unroll
                for (int ks = 0; ks < 4; ks++)
                    mma_bf16(S[nb], qh[ks], kh[cur][2 * ks], kh[cur][2 * ks + 1]);
#pragma unroll
                for (int ks = 0; ks < 4; ks++)
                    mma_bf16(S[nb], qh[ks], kl[cur][2 * ks], kl[cur][2 * ks + 1]);
#pragma unroll
                for (int ks = 0; ks < 4; ks++)
                    mma_bf16(S[nb], ql[ks], kh[cur][2 * ks], kh[cur][2 * ks + 1]);
            }
        }

        if (kt * 64 + 63 > rowg) {
#pragma unroll
            for (int nb = 0; nb < 8; nb++) {
                const int c0 = kt * 64 + nb * 8 + 2 * tig;
                if (c0 > rowg)         S[nb][0] = -INFINITY;
                if (c0 + 1 > rowg)     S[nb][1] = -INFINITY;
                if (c0 > rowg + 8)     S[nb][2] = -INFINITY;
                if (c0 + 1 > rowg + 8) S[nb][3] = -INFINITY;
            }
        }

        unsigned ph[4][4], pl_[4][4];
#pragma unroll
        for (int nb = 0; nb < 8; nb++) {
            const float p00 = ex2f(S[nb][0]);
            const float p01 = ex2f(S[nb][1]);
            const float p10 = ex2f(S[nb][2]);
            const float p11 = ex2f(S[nb][3]);
            l0v += p00 + p01;
            l1v += p10 + p11;
            const int ks = nb >> 1;
            const int hf = (nb & 1) * 2;
            split2(p00, p01, ph[ks][hf + 0], pl_[ks][hf + 0]);
            split2(p10, p11, ph[ks][hf + 1], pl_[ks][hf + 1]);
        }

        {
            unsigned vh[2][8], vl[2][8];
            LDB4(vh[0], vl[0], AS_VH, AS_VL, (lrow) * AP + 4 * lt);
#pragma unroll
            for (int nb = 0; nb < 8; nb++) {
                const int cur = nb & 1;
                if (nb < 7)
                    LDB4(vh[cur ^ 1], vl[cur ^ 1], AS_VH, AS_VL,
                         ((nb + 1) * 8 + lrow) * AP + 4 * lt);
#pragma unroll
                for (int ks = 0; ks < 4; ks++)
                    mma_bf16(O[nb], ph[ks], vh[cur][2 * ks], vh[cur][2 * ks + 1]);
#pragma unroll
                for (int ks = 0; ks < 4; ks++)
                    mma_bf16(O[nb], ph[ks], vl[cur][2 * ks], vl[cur][2 * ks + 1]);
#pragma unroll
                for (int ks = 0; ks < 4; ks++)
                    mma_bf16(O[nb], pl_[ks], vh[cur][2 * ks], vh[cur][2 * ks + 1]);
            }
        }
        stg = (stg + 1) % 3;
    }

    l0v += __shfl_xor_sync(0xffffffffu, l0v, 1);
    l0v += __shfl_xor_sync(0xffffffffu, l0v, 2);
    l1v += __shfl_xor_sync(0xffffffffu, l1v, 1);
    l1v += __shfl_xor_sync(0xffffffffu, l1v, 2);

    const size_t prow = (size_t)(sp * 8 + b) * S_ + q0 + w * 16 + g;
#pragma unroll
    for (int nb = 0; nb < 8; nb++) {
        const int d = nb * 8 + 2 * tig;
        *(float2*)&g_Op[prow * 64 + d]       = make_float2(O[nb][0], O[nb][1]);
        *(float2*)&g_Op[(prow + 8) * 64 + d] = make_float2(O[nb][2], O[nb][3]);
    }
    if (tig == 0) {
        g_pl[prow] = l0v;
        g_pl[prow + 8] = l1v;
    }
}

// ---------------------------------------------------------------------------
// Combine the 4 KV splits. One float4 per thread, grid 1024x256 -> MLP 4.
// ---------------------------------------------------------------------------
__global__ __launch_bounds__(256) void combine_kernel(float* __restrict__ out)
{
    const int idx = blockIdx.x * 256 + threadIdx.x;   // 0..262143
    const int rg  = idx >> 4;                          // row
    const int c   = (idx & 15) * 4;                    // col offset
    float4 o0 = *(const float4*)&g_Op[((size_t)0 * MTOT + rg) * DK + c];
    float4 o1 = *(const float4*)&g_Op[((size_t)1 * MTOT + rg) * DK + c];
    float4 o2 = *(const float4*)&g_Op[((size_t)2 * MTOT + rg) * DK + c];
    float4 o3 = *(const float4*)&g_Op[((size_t)3 * MTOT + rg) * DK + c];
    const float inv = 1.0f / (g_pl[rg] + g_pl[MTOT + rg] +
                              g_pl[2 * MTOT + rg] + g_pl[3 * MTOT + rg]);
    float4 r;
    r.x = (o0.x + o1.x + o2.x + o3.x) * inv;
    r.y = (o0.y + o1.y + o2.y + o3.y) * inv;
    r.z = (o0.z + o1.z + o2.z + o3.z) * inv;
    r.w = (o0.w + o1.w + o2.w + o3.w) * inv;
    *(float4*)&out[(size_t)rg * DK + c] = r;
}

// ---------------------------------------------------------------------------
extern "C" void kernel_launch(void* const* d_in, const int* in_sizes, int n_in,
                              void* d_out, int out_size)
{
    const float* X  = (const float*)d_in[0];
    const float* Wq = (const float*)d_in[1];
    const float* Wk = (const float*)d_in[2];
    const float* Wv = (const float*)d_in[3];
    float* out = (float*)d_out;

    cvt_w_kernel<<<dim3(8, 3), 256>>>(Wq, Wk, Wv);

    const int qsm = 2 * QSTAGE * 4;   // 71680 B
    cudaFuncSetAttribute(qkv_mma_kernel,
                         cudaFuncAttributeMaxDynamicSharedMemorySize, qsm);
    qkv_mma_kernel<<<(MTOT / 128) * 2, 256, qsm>>>(X);

    const int asm_ = 3 * ASTAGE * 4;  // 110592 B
    cudaFuncSetAttribute(attn_kernel,
                         cudaFuncAttributeMaxDynamicSharedMemorySize, asm_);
    attn_kernel<<<8 * NSP * (S_ / 128), 256, asm_>>>();

    combine_kernel<<<MTOT * DK / 4 / 256, 256>>>(out);
}